// round 17
// baseline (speedup 1.0000x reference)
#include <cuda_runtime.h>
#include <cuda_bf16.h>
#include <cstdint>

// ---------------------------------------------------------------------------
// DIN forward.
//  Kernel PF: fused pre-split (item_table/w2/mlp weights) + per-b weight fold
//  Kernel A : FUSED scores + softmax + interest. One CTA per b, 416 thr
//             (13 warps x m16 covering 208 rows), 93KB smem, 2 CTAs/SM.
//  Kernel C : final MLP via bf16 MMA, 512 thr (16 warps)
// ---------------------------------------------------------------------------

#define B_ROWS 4096
#define T_LEN  200
#define TPAD   224
#define E_DIM  64
#define VOCAB_ITEM 100000
#define PACK_BLOCKS ((VOCAB_ITEM * 32 + 255) / 256)
#define NTHRA  416

__device__ uint32_t g_keyH[VOCAB_ITEM * 32];    // packed bf16-hi pairs per row
__device__ uint32_t g_keyL[VOCAB_ITEM * 32];    // packed bf16-lo pairs
__device__ uint32_t g_w12H[B_ROWS * 2048];      // [b][j][w] packed pairs
__device__ uint32_t g_w12L[B_ROWS * 2048];
__device__ uint32_t g_w2H[1024];                // [n][w]
__device__ uint32_t g_w2L[1024];
__device__ uint32_t g_m1H[256 * 136];           // mlp_w1 [n][w] packed pairs
__device__ uint32_t g_m1L[256 * 136];
__device__ uint32_t g_m2H[128 * 128];           // mlp_w2 [n][w]
__device__ uint32_t g_m2L[128 * 128];
__device__ float g_qc[B_ROWS * 64];
__device__ float g_interest[B_ROWS * E_DIM];

// ---- bf16 split helpers ----
__device__ __forceinline__ void bsplit(float x, uint16_t& h, uint16_t& l) {
    __nv_bfloat16 bh = __float2bfloat16(x);
    float r = x - __bfloat162float(bh);
    __nv_bfloat16 bl = __float2bfloat16(r);
    h = *reinterpret_cast<uint16_t*>(&bh);
    l = *reinterpret_cast<uint16_t*>(&bl);
}
__device__ __forceinline__ uint32_t packu(uint16_t lo, uint16_t hi) {
    return (uint32_t)lo | ((uint32_t)hi << 16);
}
__device__ __forceinline__ void bsplit2(float e, float o, uint32_t& wh, uint32_t& wl) {
    uint16_t eh, el, oh, ol;
    bsplit(e, eh, el);
    bsplit(o, oh, ol);
    wh = packu(eh, oh);
    wl = packu(el, ol);
}

// D += A*B  (m16n8k16, A row-major, B col-major, bf16 in, f32 acc)
__device__ __forceinline__ void mmabf(float* d, const uint32_t* a, const uint32_t* b) {
    asm volatile(
        "mma.sync.aligned.m16n8k16.row.col.f32.bf16.bf16.f32 "
        "{%0,%1,%2,%3}, {%4,%5,%6,%7}, {%8,%9}, {%0,%1,%2,%3};"
        : "+f"(d[0]), "+f"(d[1]), "+f"(d[2]), "+f"(d[3])
        : "r"(a[0]), "r"(a[1]), "r"(a[2]), "r"(a[3]), "r"(b[0]), "r"(b[1]));
}

// ---------------------------------------------------------------------------
// Kernel PF: fused pack (blocks < PACK_BLOCKS) + fold (remaining B_ROWS blocks)
// ---------------------------------------------------------------------------
__global__ void __launch_bounds__(256)
din_prep_kernel(const int* __restrict__ tgt,
                const float* __restrict__ item_table,
                const float* __restrict__ w1, const float* __restrict__ b1,
                const float* __restrict__ w2,
                const float* __restrict__ m1,   // mlp_w1 [272][256]
                const float* __restrict__ m2)   // mlp_w2 [256][128]
{
    __shared__ float Q[64];
    __shared__ float SM[64 * 65];
    const int tid = threadIdx.x;

    if (blockIdx.x < PACK_BLOCKS) {
        long i = (long)blockIdx.x * 256 + tid;
        if (i < (long)VOCAB_ITEM * 32) {
            float2 v = ((const float2*)item_table)[i];
            uint32_t h, l;
            bsplit2(v.x, v.y, h, l);
            g_keyH[i] = h;
            g_keyL[i] = l;
        }
        if (i < 1024) {
            int n = (int)i & 31, w = (int)i >> 5;
            float e = w2[(2 * w) * 32 + n];
            float o = w2[(2 * w + 1) * 32 + n];
            uint32_t h, l;
            bsplit2(e, o, h, l);
            g_w2H[n * 32 + w] = h;
            g_w2L[n * 32 + w] = l;
        }
        if (i < 256 * 136) {
            int n = (int)(i / 136), w = (int)(i % 136);
            float e = m1[(2 * w) * 256 + n];
            float o = m1[(2 * w + 1) * 256 + n];
            uint32_t h, l;
            bsplit2(e, o, h, l);
            g_m1H[i] = h;
            g_m1L[i] = l;
        }
        if (i < 128 * 128) {
            int n = (int)(i >> 7), w = (int)(i & 127);
            float e = m2[(2 * w) * 128 + n];
            float o = m2[(2 * w + 1) * 128 + n];
            uint32_t h, l;
            bsplit2(e, o, h, l);
            g_m2H[i] = h;
            g_m2L[i] = l;
        }
        return;
    }

    const int b = blockIdx.x - PACK_BLOCKS;

    if (tid < 64) Q[tid] = item_table[(long)tgt[b] * 64 + tid];
    __syncthreads();

    for (int i = tid; i < 4096; i += 256) {
        int k = i >> 6, j = i & 63;
        SM[k * 65 + j] = w1[i] + w1[8192 + i] + Q[k] * w1[12288 + i];
    }
    __syncthreads();
    for (int i = tid; i < 2048; i += 256) {
        int j = i >> 5, w = i & 31;
        float e = SM[(2 * w) * 65 + j];
        float o = SM[(2 * w + 1) * 65 + j];
        uint32_t h, l;
        bsplit2(e, o, h, l);
        g_w12H[(long)b * 2048 + i] = h;
        g_w12L[(long)b * 2048 + i] = l;
    }
    if (tid < 64) {
        float s = b1[tid];
        #pragma unroll 8
        for (int e = 0; e < 64; ++e)
            s += Q[e] * (w1[4096 + e * 64 + tid] - w1[8192 + e * 64 + tid]);
        g_qc[b * 64 + tid] = s;
    }
}

// ---------------------------------------------------------------------------
// Kernel A: FUSED scores + softmax + interest. One CTA per b, 13 warps.
// smem (u32 words):
//   KH[208][36]=7488 @0 (alias H1H) | KL @7488 (alias H1L)
//   W12H @14976 | W12L @17280 | W2H @19584 | W2L @20736
//   QC @21888 | B2 @21952 | WO @21984 | SC @22016 | WG @22240
//   RED @22464 | SV @22480 | ACC[13][64] @22484
// ---------------------------------------------------------------------------
#define SA_KH    0
#define SA_KL    7488
#define SA_W12H  14976
#define SA_W12L  17280
#define SA_W2H   19584
#define SA_W2L   20736
#define SA_QC    21888
#define SA_B2    21952
#define SA_WO    21984
#define SA_SC    22016
#define SA_WG    22240
#define SA_RED   22464
#define SA_SV    22480
#define SA_ACC   22484
#define SMEMA_WORDS (22484 + 832)
#define SMEMA_BYTES (SMEMA_WORDS * 4)

__global__ void __launch_bounds__(NTHRA, 2)
din_attn_kernel(const int* __restrict__ hist,
                const int* __restrict__ mask,
                const float* __restrict__ item_table,
                const float* __restrict__ b2,
                const float* __restrict__ wo, const float* __restrict__ bo)
{
    extern __shared__ uint32_t smu[];
    uint32_t* KH   = smu + SA_KH;     // aliased by H1H after A-frag hoist
    uint32_t* KL   = smu + SA_KL;     // aliased by H1L
    uint32_t* W12H = smu + SA_W12H;
    uint32_t* W12L = smu + SA_W12L;
    uint32_t* W2H  = smu + SA_W2H;
    uint32_t* W2L  = smu + SA_W2L;
    float*    QC   = (float*)(smu + SA_QC);
    float*    B2S  = (float*)(smu + SA_B2);
    float*    WOS  = (float*)(smu + SA_WO);
    float*    SC   = (float*)(smu + SA_SC);
    float*    WG   = (float*)(smu + SA_WG);
    float*    RED  = (float*)(smu + SA_RED);
    float*    SV   = (float*)(smu + SA_SV);
    float*    ACC  = (float*)(smu + SA_ACC);

    const int b    = blockIdx.x;
    const int tid  = threadIdx.x;
    const int lane = tid & 31;
    const int wid  = tid >> 5;      // 0..12
    const int gid  = lane >> 2;     // 0..7
    const int tig  = lane & 3;      // 0..3

    // ---- stage operands (pure copies) ----
    {
        const uint4* HV = (const uint4*)g_keyH;
        const uint4* LV = (const uint4*)g_keyL;
        for (int i = tid; i < 208 * 8; i += NTHRA) {
            int f = i & 7, m = i >> 3;
            uint4 h = make_uint4(0u, 0u, 0u, 0u);
            uint4 l = make_uint4(0u, 0u, 0u, 0u);
            if (m < T_LEN) {
                int row = hist[b * T_LEN + m];
                h = HV[row * 8 + f];
                l = LV[row * 8 + f];
            }
            *(uint4*)(KH + m * 36 + 4 * f) = h;
            *(uint4*)(KL + m * 36 + 4 * f) = l;
        }
        const uint4* WH = (const uint4*)(g_w12H + (long)b * 2048);
        const uint4* WL = (const uint4*)(g_w12L + (long)b * 2048);
        for (int i = tid; i < 64 * 8; i += NTHRA) {
            int f = i & 7, j = i >> 3;
            *(uint4*)(W12H + j * 36 + 4 * f) = WH[i];
            *(uint4*)(W12L + j * 36 + 4 * f) = WL[i];
        }
        const uint4* VH = (const uint4*)g_w2H;
        const uint4* VL = (const uint4*)g_w2L;
        if (tid < 256) {
            int i = tid;
            int f = i & 7, n = i >> 3;
            *(uint4*)(W2H + n * 36 + 4 * f) = VH[i];
            *(uint4*)(W2L + n * 36 + 4 * f) = VL[i];
        }
    }
    if (tid < 64) QC[tid] = g_qc[b * 64 + tid];
    if (tid < 32) { B2S[tid] = b2[tid]; WOS[tid] = wo[tid]; }
    if (tid >= 200 && tid < TPAD) SC[tid] = -1e9f;   // pad rows
    __syncthreads();

    const int mb = wid * 16;

    // ---- GEMM1: H1[m][j] = relu(KEYS @ W12T^T + qc) ----
    uint32_t ah[4][4], al[4][4];
    #pragma unroll
    for (int kc = 0; kc < 4; ++kc) {
        int a0 = (mb + gid) * 36 + kc * 8 + tig;
        int a1 = (mb + gid + 8) * 36 + kc * 8 + tig;
        ah[kc][0] = KH[a0]; ah[kc][1] = KH[a1];
        ah[kc][2] = KH[a0 + 4]; ah[kc][3] = KH[a1 + 4];
        al[kc][0] = KL[a0]; al[kc][1] = KL[a1];
        al[kc][2] = KL[a0 + 4]; al[kc][3] = KL[a1 + 4];
    }
    __syncthreads();   // KEYS dead; smem becomes H1

    {
        #pragma unroll
        for (int nt = 0; nt < 8; ++nt) {
            float acc[4] = {0.f, 0.f, 0.f, 0.f};
            #pragma unroll
            for (int kc = 0; kc < 4; ++kc) {
                const int boff = (nt * 8 + gid) * 36 + kc * 8 + tig;
                uint32_t bh[2], bl[2];
                bh[0] = W12H[boff]; bh[1] = W12H[boff + 4];
                bl[0] = W12L[boff]; bl[1] = W12L[boff + 4];
                mmabf(acc, ah[kc], bh);
                mmabf(acc, ah[kc], bl);
                mmabf(acc, al[kc], bh);
            }
            int j0 = nt * 8 + 2 * tig;
            float q0 = QC[j0], q1 = QC[j0 + 1];
            float v0 = fmaxf(acc[0] + q0, 0.f);
            float v1 = fmaxf(acc[1] + q1, 0.f);
            float v2 = fmaxf(acc[2] + q0, 0.f);
            float v3 = fmaxf(acc[3] + q1, 0.f);
            uint32_t h01, l01, h23, l23;
            bsplit2(v0, v1, h01, l01);
            bsplit2(v2, v3, h23, l23);
            KH[(mb + gid) * 36 + nt * 4 + tig]     = h01;  // H1H
            KL[(mb + gid) * 36 + nt * 4 + tig]     = l01;  // H1L
            KH[(mb + gid + 8) * 36 + nt * 4 + tig] = h23;
            KL[(mb + gid + 8) * 36 + nt * 4 + tig] = l23;
        }
    }
    __syncwarp();   // H1 rows are warp-private

    // ---- GEMM2: scores = reduce_n relu(H1 @ W2T^T + b2)*wo -> SC (smem) ----
    {
        uint32_t ch[4][4], cl[4][4];
        #pragma unroll
        for (int kc = 0; kc < 4; ++kc) {
            int a0 = (mb + gid) * 36 + kc * 8 + tig;
            int a1 = (mb + gid + 8) * 36 + kc * 8 + tig;
            ch[kc][0] = KH[a0]; ch[kc][1] = KH[a1];
            ch[kc][2] = KH[a0 + 4]; ch[kc][3] = KH[a1 + 4];
            cl[kc][0] = KL[a0]; cl[kc][1] = KL[a1];
            cl[kc][2] = KL[a0 + 4]; cl[kc][3] = KL[a1 + 4];
        }
        float srow0 = 0.f, srow8 = 0.f;
        #pragma unroll
        for (int nt = 0; nt < 4; ++nt) {
            float acc[4] = {0.f, 0.f, 0.f, 0.f};
            #pragma unroll
            for (int kc = 0; kc < 4; ++kc) {
                const int boff = (nt * 8 + gid) * 36 + kc * 8 + tig;
                uint32_t bh[2], bl[2];
                bh[0] = W2H[boff]; bh[1] = W2H[boff + 4];
                bl[0] = W2L[boff]; bl[1] = W2L[boff + 4];
                mmabf(acc, ch[kc], bh);
                mmabf(acc, ch[kc], bl);
                mmabf(acc, cl[kc], bh);
            }
            int n0 = nt * 8 + 2 * tig;
            float bb0 = B2S[n0], bb1 = B2S[n0 + 1];
            float w0 = WOS[n0],  w1v = WOS[n0 + 1];
            srow0 += fmaxf(acc[0] + bb0, 0.f) * w0 + fmaxf(acc[1] + bb1, 0.f) * w1v;
            srow8 += fmaxf(acc[2] + bb0, 0.f) * w0 + fmaxf(acc[3] + bb1, 0.f) * w1v;
        }
        srow0 += __shfl_xor_sync(0xffffffffu, srow0, 1);
        srow0 += __shfl_xor_sync(0xffffffffu, srow0, 2);
        srow8 += __shfl_xor_sync(0xffffffffu, srow8, 1);
        srow8 += __shfl_xor_sync(0xffffffffu, srow8, 2);

        if (tig == 0) {
            float bos = bo[0];
            int tg0 = mb + gid;
            int tg8 = tg0 + 8;
            if (tg0 < T_LEN)
                SC[tg0] = mask[b * T_LEN + tg0] ? srow0 + bos : -1e9f;
            if (tg8 < T_LEN)
                SC[tg8] = mask[b * T_LEN + tg8] ? srow8 + bos : -1e9f;
        }
    }
    __syncthreads();

    // ---- softmax over 224 (13 warps) ----
    {
        float s = (tid < TPAD) ? SC[tid] : -3.4e38f;
        float m = s;
        #pragma unroll
        for (int off = 16; off > 0; off >>= 1)
            m = fmaxf(m, __shfl_xor_sync(0xffffffffu, m, off));
        if (lane == 0) RED[wid] = m;
        __syncthreads();
        if (wid == 0) {
            float mm = (lane < 7) ? RED[lane] : -3.4e38f;   // warps 0..6 hold tid<224
            #pragma unroll
            for (int off = 4; off > 0; off >>= 1)
                mm = fmaxf(mm, __shfl_xor_sync(0xffffffffu, mm, off));
            if (lane == 0) SV[0] = mm;
        }
        __syncthreads();
        float e = 0.f;
        if (tid < TPAD) {
            e = expf(SC[tid] - SV[0]);
            WG[tid] = e;
        }
        #pragma unroll
        for (int off = 16; off > 0; off >>= 1)
            e += __shfl_xor_sync(0xffffffffu, e, off);
        if (lane == 0) RED[wid] = e;
        __syncthreads();
        if (wid == 0) {
            float t2 = (lane < 7) ? RED[lane] : 0.f;
            #pragma unroll
            for (int off = 4; off > 0; off >>= 1)
                t2 += __shfl_xor_sync(0xffffffffu, t2, off);
            if (lane == 0) SV[1] = t2;
        }
        __syncthreads();
    }

    // ---- interest: warp w owns t in [16w, 16w+16); lane owns e-pair ----
    {
        float a0 = 0.f, a1 = 0.f;
        #pragma unroll
        for (int i = 0; i < 16; ++i) {
            int t = wid * 16 + i;
            if (t < T_LEN) {
                float wv = WG[t];
                int row = hist[b * T_LEN + t];
                float2 v = *(const float2*)(item_table + (long)row * E_DIM + 2 * lane);
                a0 += wv * v.x;
                a1 += wv * v.y;
            }
        }
        *(float2*)(ACC + wid * 64 + 2 * lane) = make_float2(a0, a1);
    }
    __syncthreads();
    if (tid < 64) {
        float v = 0.f;
        #pragma unroll
        for (int w = 0; w < 13; ++w) v += ACC[w * 64 + tid];
        g_interest[(long)b * E_DIM + tid] = v / SV[1];
    }
}

// ---------------------------------------------------------------------------
// Kernel C: final MLP via bf16 MMA. 16 rows/CTA, 512 thr (16 warps), grid 256.
// GEMM1: warp owns n16; GEMM2: warp owns n8.
// ---------------------------------------------------------------------------
#define MC_AH   0
#define MC_AL   2240
#define MC_H2H  4480
#define MC_H2L  (4480 + 2112)
#define MC_B1   (4480 + 4224)
#define MC_B2   (MC_B1 + 256)
#define MC_WO   (MC_B2 + 128)
#define MC_R    (MC_WO + 128)
#define SMEMC_WORDS (MC_R + 256)
#define SMEMC_BYTES (SMEMC_WORDS * 4)

__global__ void __launch_bounds__(512, 2)
din_mlp_kernel(const int* __restrict__ tgt,
               const int* __restrict__ sf,
               const float* __restrict__ dense,
               const float* __restrict__ item_table,
               const float* __restrict__ user_table,
               const float* __restrict__ ctx_table,
               const float* __restrict__ b1, const float* __restrict__ b2,
               const float* __restrict__ ow, const float* __restrict__ ob,
               float* __restrict__ out)
{
    extern __shared__ uint32_t smw[];
    uint32_t* AH  = smw + MC_AH;
    uint32_t* AL  = smw + MC_AL;
    uint32_t* H2H = smw + MC_H2H;
    uint32_t* H2L = smw + MC_H2L;
    float* B1S = (float*)(smw + MC_B1);
    float* B2S = (float*)(smw + MC_B2);
    float* WOS = (float*)(smw + MC_WO);
    float* R   = (float*)(smw + MC_R);

    const int b0   = blockIdx.x * 16;
    const int tid  = threadIdx.x;
    const int lane = tid & 31;
    const int wid  = tid >> 5;      // 0..15
    const int gid  = lane >> 2;     // 0..7
    const int tig  = lane & 3;      // 0..3

    // ---- stage features as packed bf16 hi/lo pairs ----
    for (int i = tid; i < 16 * 136; i += 512) {
        int bb = i / 136, w = i % 136;
        int gb = b0 + bb;
        int k = 2 * w;
        float e, o;
        if (k < 64) {
            const float* p = user_table + (long)sf[gb * 2] * 64 + k;
            e = p[0]; o = p[1];
        } else if (k < 128) {
            const float* p = ctx_table + (long)sf[gb * 2 + 1] * 64 + (k - 64);
            e = p[0]; o = p[1];
        } else if (k < 192) {
            const float* p = item_table + (long)tgt[gb] * 64 + (k - 128);
            e = p[0]; o = p[1];
        } else if (k < 256) {
            const float* p = g_interest + (long)gb * 64 + (k - 192);
            e = p[0]; o = p[1];
        } else {
            const float* p = dense + gb * 16 + (k - 256);
            e = p[0]; o = p[1];
        }
        uint32_t h, l;
        bsplit2(e, o, h, l);
        AH[bb * 140 + w] = h;
        AL[bb * 140 + w] = l;
    }
    if (tid < 256) B1S[tid] = b1[tid];
    if (tid < 128) { B2S[tid] = b2[tid]; WOS[tid] = ow[tid]; }
    __syncthreads();

    // ---- GEMM1: M16 x N256 x K272; warp owns n in [16*wid, 16*wid+16) ----
    const int n0 = wid * 16;
    {
        float acc[2][4];
        #pragma unroll
        for (int nt = 0; nt < 2; ++nt)
            #pragma unroll
            for (int p = 0; p < 4; ++p) acc[nt][p] = 0.f;

        for (int kc = 0; kc < 17; ++kc) {
            int a0 = gid * 140 + kc * 8 + tig;
            int a1 = (gid + 8) * 140 + kc * 8 + tig;
            uint32_t ah[4] = {AH[a0], AH[a1], AH[a0 + 4], AH[a1 + 4]};
            uint32_t al[4] = {AL[a0], AL[a1], AL[a0 + 4], AL[a1 + 4]};
            #pragma unroll
            for (int nt = 0; nt < 2; ++nt) {
                long boff = (long)(n0 + nt * 8 + gid) * 136 + kc * 8 + tig;
                uint32_t bh[2] = {g_m1H[boff], g_m1H[boff + 4]};
                uint32_t bl[2] = {g_m1L[boff], g_m1L[boff + 4]};
                mmabf(acc[nt], ah, bh);
                mmabf(acc[nt], ah, bl);
                mmabf(acc[nt], al, bh);
            }
        }
        // relu + b1, pack into H2 (k-pair layout for GEMM2's A, stride 132)
        #pragma unroll
        for (int nt = 0; nt < 2; ++nt) {
            int n = n0 + nt * 8 + 2 * tig;
            float q0 = B1S[n], q1 = B1S[n + 1];
            float v0 = fmaxf(acc[nt][0] + q0, 0.f);
            float v1 = fmaxf(acc[nt][1] + q1, 0.f);
            float v2 = fmaxf(acc[nt][2] + q0, 0.f);
            float v3 = fmaxf(acc[nt][3] + q1, 0.f);
            uint32_t h01, l01, h23, l23;
            bsplit2(v0, v1, h01, l01);
            bsplit2(v2, v3, h23, l23);
            int pw = (n0 >> 1) + nt * 4 + tig;      // pair index 0..127
            H2H[gid * 132 + pw]       = h01;
            H2L[gid * 132 + pw]       = l01;
            H2H[(gid + 8) * 132 + pw] = h23;
            H2L[(gid + 8) * 132 + pw] = l23;
        }
    }
    __syncthreads();

    // ---- GEMM2: M16 x N128 x K256; warp owns n in [8*wid, 8*wid+8) ----
    {
        const int n0b = wid * 8;
        float acc[4] = {0.f, 0.f, 0.f, 0.f};

        for (int kc = 0; kc < 16; ++kc) {
            int a0 = gid * 132 + kc * 8 + tig;
            int a1 = (gid + 8) * 132 + kc * 8 + tig;
            uint32_t ah[4] = {H2H[a0], H2H[a1], H2H[a0 + 4], H2H[a1 + 4]};
            uint32_t al[4] = {H2L[a0], H2L[a1], H2L[a0 + 4], H2L[a1 + 4]};
            long boff = (long)(n0b + gid) * 128 + kc * 8 + tig;
            uint32_t bh[2] = {g_m2H[boff], g_m2H[boff + 4]};
            uint32_t bl[2] = {g_m2L[boff], g_m2L[boff + 4]};
            mmabf(acc, ah, bh);
            mmabf(acc, ah, bl);
            mmabf(acc, al, bh);
        }
        int n = n0b + 2 * tig;
        float bb0 = B2S[n], bb1 = B2S[n + 1];
        float w0 = WOS[n],  w1v = WOS[n + 1];
        float s0 = fmaxf(acc[0] + bb0, 0.f) * w0 + fmaxf(acc[1] + bb1, 0.f) * w1v;
        float s8 = fmaxf(acc[2] + bb0, 0.f) * w0 + fmaxf(acc[3] + bb1, 0.f) * w1v;
        s0 += __shfl_xor_sync(0xffffffffu, s0, 1);
        s0 += __shfl_xor_sync(0xffffffffu, s0, 2);
        s8 += __shfl_xor_sync(0xffffffffu, s8, 1);
        s8 += __shfl_xor_sync(0xffffffffu, s8, 2);
        if (tig == 0) {
            R[wid * 16 + gid]     = s0;
            R[wid * 16 + gid + 8] = s8;
        }
    }
    __syncthreads();
    if (tid < 16) {
        float s = ob[0];
        #pragma unroll
        for (int w = 0; w < 16; ++w) s += R[w * 16 + tid];
        out[b0 + tid] = s;
    }
}

// ---------------------------------------------------------------------------
extern "C" void kernel_launch(void* const* d_in, const int* in_sizes, int n_in,
                              void* d_out, int out_size)
{
    const int*   tgt   = (const int*)d_in[0];
    const int*   hist  = (const int*)d_in[1];
    const int*   mask  = (const int*)d_in[2];
    const int*   sf    = (const int*)d_in[3];
    const float* dense = (const float*)d_in[4];
    const float* item_table = (const float*)d_in[5];
    const float* user_table = (const float*)d_in[6];
    const float* ctx_table  = (const float*)d_in[7];
    const float* att_w1 = (const float*)d_in[8];
    const float* att_b1 = (const float*)d_in[9];
    const float* att_w2 = (const float*)d_in[10];
    const float* att_b2 = (const float*)d_in[11];
    const float* att_wo = (const float*)d_in[12];
    const float* att_bo = (const float*)d_in[13];
    const float* mlp_w1 = (const float*)d_in[14];
    const float* mlp_b1 = (const float*)d_in[15];
    const float* mlp_w2 = (const float*)d_in[16];
    const float* mlp_b2 = (const float*)d_in[17];
    const float* out_w  = (const float*)d_in[18];
    const float* out_b  = (const float*)d_in[19];
    float*       out    = (float*)d_out;

    cudaFuncSetAttribute(din_attn_kernel, cudaFuncAttributeMaxDynamicSharedMemorySize, SMEMA_BYTES);
    cudaFuncSetAttribute(din_mlp_kernel,  cudaFuncAttributeMaxDynamicSharedMemorySize, SMEMC_BYTES);

    din_prep_kernel<<<PACK_BLOCKS + B_ROWS, 256>>>(
        tgt, item_table, att_w1, att_b1, att_w2, mlp_w1, mlp_w2);

    din_attn_kernel<<<B_ROWS, NTHRA, SMEMA_BYTES>>>(
        hist, mask, item_table, att_b2, att_wo, att_bo);

    din_mlp_kernel<<<B_ROWS / 16, 512, SMEMC_BYTES>>>(
        tgt, sf, dense, item_table, user_table, ctx_table,
        mlp_b1, mlp_b2, out_w, out_b, out);
}